// round 1
// baseline (speedup 1.0000x reference)
#include <cuda_runtime.h>

#define NTOKEN 33278
#define NINP   400
#define NHID   1150
#define NHP    1152          // padded row stride (float4-friendly)
#define SLEN   70
#define BATCH  128
#define NS     10
#define SB     (SLEN*BATCH)  // 8960
#define TEMP   65.0f
#define EPSV   1e-6f

// ---------------- device scratch (static, no allocation) ----------------
__device__ __align__(16) float Egl[(size_t)NTOKEN * NHP];        // 153 MB: emb_W @ W_ih^T + b_ih
__device__ __align__(16) float RO[(size_t)(SLEN + 1) * BATCH * NHP]; // 42 MB: all hidden states
__device__ __align__(16) float HU[(size_t)SLEN * BATCH * NHP];   // 41 MB: h_t @ W_hh^T + b_hh
__device__ __align__(16) float WHH[NHP * NHP];                   // padded W_hh
__device__ __align__(16) float WIH[NHP * NINP];                  // padded W_ih
__device__ __align__(16) float HUP[4 * BATCH * NHP];             // split-K partials
__device__ float NEGS[SB];
__device__ double ACCpos, ACClog, ACCbias;

// ---------------- f32x2 packed-FMA helpers (Blackwell FFMA2) ----------------
typedef unsigned long long ull;
__device__ __forceinline__ ull pack2(float x, float y) {
    ull u; asm("mov.b64 %0, {%1, %2};" : "=l"(u) : "f"(x), "f"(y)); return u;
}
__device__ __forceinline__ float2 unpack2(ull u) {
    float2 r; asm("mov.b64 {%0, %1}, %2;" : "=f"(r.x), "=f"(r.y) : "l"(u)); return r;
}
__device__ __forceinline__ void fma2(ull &d, ull a, ull b) {
    asm("fma.rn.f32x2 %0, %1, %2, %3;" : "=l"(d) : "l"(a), "l"(b), "l"(d));
}
__device__ __forceinline__ float tanh_fast(float x) {
    float r; asm("tanh.approx.f32 %0, %1;" : "=f"(r) : "f"(x)); return r;
}

// ---------------- init ----------------
__global__ void k_zero() {
    size_t i = (size_t)blockIdx.x * blockDim.x + threadIdx.x;
    size_t stride = (size_t)gridDim.x * blockDim.x;
    const size_t n = (size_t)(SLEN + 1) * BATCH * NHP;
    for (size_t idx = i; idx < n; idx += stride) RO[idx] = 0.f;
    if (i == 0) { ACCpos = 0.0; ACClog = 0.0; ACCbias = 0.0; }
}

__global__ void k_prep(const float* __restrict__ W_hh, const float* __restrict__ W_ih,
                       const float* __restrict__ hidden) {
    int i = blockIdx.x * blockDim.x + threadIdx.x;
    int stride = gridDim.x * blockDim.x;
    const int nwhh = NHP * NHP;
    const int nwih = NHP * NINP;
    const int nhid = BATCH * NHID;
    for (int idx = i; idx < nwhh + nwih + nhid; idx += stride) {
        if (idx < nwhh) {
            int r = idx / NHP, c = idx % NHP;
            WHH[idx] = (r < NHID && c < NHID) ? W_hh[r * NHID + c] : 0.f;
        } else if (idx < nwhh + nwih) {
            int j = idx - nwhh; int r = j / NINP;
            WIH[j] = (r < NHID) ? W_ih[j] : 0.f;
        } else {
            int j = idx - nwhh - nwih;
            int b = j / NHID, c = j % NHID;
            RO[(size_t)b * NHP + c] = hidden[j];
        }
    }
}

// ---------------- E = emb_W @ W_ih^T + b_ih  (M=33278, N=1152pad, K=400) ----------------
// 128x128 block tile, 8x8 micro tile via f32x2, 256 threads.
__global__ __launch_bounds__(256, 2) void k_egemm(const float* __restrict__ A,
                                                  const float* __restrict__ bih) {
    __shared__ float As[16][132];   // [k][m]
    __shared__ float Bs[16][132];   // [k][n]
    const int bm = blockIdx.y * 128;
    const int bn = blockIdx.x * 128;
    const int tid = threadIdx.x;
    const int tx = tid & 15, ty = tid >> 4;

    ull acc[8][4];
    #pragma unroll
    for (int i = 0; i < 8; i++)
        #pragma unroll
        for (int j = 0; j < 4; j++) acc[i][j] = 0ULL;

    for (int k0 = 0; k0 < NINP; k0 += 16) {
        #pragma unroll
        for (int l = 0; l < 2; l++) {
            int f = tid + l * 256;
            int r = f >> 2, c4 = (f & 3) * 4;
            float4 va = make_float4(0.f, 0.f, 0.f, 0.f);
            int m = bm + r;
            if (m < NTOKEN) va = *(const float4*)(A + (size_t)m * NINP + k0 + c4);
            As[c4 + 0][r] = va.x; As[c4 + 1][r] = va.y; As[c4 + 2][r] = va.z; As[c4 + 3][r] = va.w;
            float4 vb = *(const float4*)(WIH + (size_t)(bn + r) * NINP + k0 + c4);
            Bs[c4 + 0][r] = vb.x; Bs[c4 + 1][r] = vb.y; Bs[c4 + 2][r] = vb.z; Bs[c4 + 3][r] = vb.w;
        }
        __syncthreads();
        #pragma unroll
        for (int kk = 0; kk < 16; kk++) {
            float4 a0 = *(const float4*)&As[kk][ty * 8];
            float4 a1 = *(const float4*)&As[kk][ty * 8 + 4];
            float4 b0 = *(const float4*)&Bs[kk][tx * 8];
            float4 b1 = *(const float4*)&Bs[kk][tx * 8 + 4];
            ull bb[4] = { pack2(b0.x, b0.y), pack2(b0.z, b0.w),
                          pack2(b1.x, b1.y), pack2(b1.z, b1.w) };
            float am[8] = {a0.x, a0.y, a0.z, a0.w, a1.x, a1.y, a1.z, a1.w};
            #pragma unroll
            for (int i = 0; i < 8; i++) {
                ull ad = pack2(am[i], am[i]);
                #pragma unroll
                for (int j = 0; j < 4; j++) fma2(acc[i][j], ad, bb[j]);
            }
        }
        __syncthreads();
    }
    #pragma unroll
    for (int i = 0; i < 8; i++) {
        int m = bm + ty * 8 + i;
        if (m >= NTOKEN) continue;
        float* crow = Egl + (size_t)m * NHP;
        #pragma unroll
        for (int j = 0; j < 4; j++) {
            float2 v = unpack2(acc[i][j]);
            int n = bn + tx * 8 + j * 2;
            if (n     < NHID) crow[n]     = v.x + bih[n];
            if (n + 1 < NHID) crow[n + 1] = v.y + bih[n + 1];
        }
    }
}

// ---------------- scan step, phase A: split-K recurrent GEMM ----------------
// partial[z][m][n] = sum_{k in chunk z} RO[t][m][k] * WHH[n][k]
// grid (18, 2, 4): 64x64 tile, K-chunks of 288. 4x4 micro via f32x2.
__global__ __launch_bounds__(256) void k_stepA(int t) {
    const float* Arow = RO + (size_t)t * BATCH * NHP;
    const int bn = blockIdx.x * 64;
    const int bm = blockIdx.y * 64;
    const int kz = blockIdx.z;
    __shared__ float As[16][68], Bs[16][68];
    const int tid = threadIdx.x, tx = tid & 15, ty = tid >> 4;

    ull acc[4][2] = {{0ULL,0ULL},{0ULL,0ULL},{0ULL,0ULL},{0ULL,0ULL}};

    const int kend = kz * 288 + 288;
    for (int k0 = kz * 288; k0 < kend; k0 += 16) {
        int r = tid >> 2, c4 = (tid & 3) * 4;
        float4 va = *(const float4*)(Arow + (size_t)(bm + r) * NHP + k0 + c4);
        As[c4 + 0][r] = va.x; As[c4 + 1][r] = va.y; As[c4 + 2][r] = va.z; As[c4 + 3][r] = va.w;
        float4 vb = *(const float4*)(WHH + (size_t)(bn + r) * NHP + k0 + c4);
        Bs[c4 + 0][r] = vb.x; Bs[c4 + 1][r] = vb.y; Bs[c4 + 2][r] = vb.z; Bs[c4 + 3][r] = vb.w;
        __syncthreads();
        #pragma unroll
        for (int kk = 0; kk < 16; kk++) {
            float4 a = *(const float4*)&As[kk][ty * 4];
            float4 b = *(const float4*)&Bs[kk][tx * 4];
            ull b2[2] = { pack2(b.x, b.y), pack2(b.z, b.w) };
            float am[4] = {a.x, a.y, a.z, a.w};
            #pragma unroll
            for (int i = 0; i < 4; i++) {
                ull ad = pack2(am[i], am[i]);
                fma2(acc[i][0], ad, b2[0]);
                fma2(acc[i][1], ad, b2[1]);
            }
        }
        __syncthreads();
    }
    float* P = HUP + (size_t)kz * BATCH * NHP;
    #pragma unroll
    for (int i = 0; i < 4; i++) {
        int m = bm + ty * 4 + i;
        float* prow = P + (size_t)m * NHP;
        #pragma unroll
        for (int j = 0; j < 2; j++) {
            float2 v = unpack2(acc[i][j]);
            int n = bn + tx * 4 + j * 2;
            prow[n] = v.x; prow[n + 1] = v.y;
        }
    }
}

// ---------------- scan step, phase B: combine + bias + emb + tanh ----------------
__global__ void k_stepB(int t, const int* __restrict__ data, const float* __restrict__ bhh) {
    int i = blockIdx.x * blockDim.x + threadIdx.x;
    if (i >= BATCH * NHID) return;
    int b = i / NHID, c = i % NHID;
    size_t off = (size_t)b * NHP + c;
    const size_t P = (size_t)BATCH * NHP;
    float hu = HUP[off] + HUP[P + off] + HUP[2 * P + off] + HUP[3 * P + off] + bhh[c];
    HU[(size_t)t * BATCH * NHP + off] = hu;
    int tok = data[t * BATCH + b];
    float pre = Egl[(size_t)tok * NHP + c] + hu;
    RO[(size_t)(t + 1) * BATCH * NHP + off] = tanhf(pre);
}

// ---------------- negative samples: NEGS[j] = sum_n exp(-TEMP*dist(n,j)) ----------------
__global__ __launch_bounds__(128) void k_neg(const int* __restrict__ samples,
                                             const float* __restrict__ bias) {
    int j = blockIdx.x;
    __shared__ float fl[NHID], hus[NHID];
    __shared__ float red[4];
    const float* flat = RO + (size_t)j * NHP;
    const float* huj  = HU + (size_t)j * NHP;
    int tid = threadIdx.x;
    for (int c = tid; c < NHID; c += 128) { fl[c] = flat[c]; hus[c] = huj[c]; }
    __syncthreads();
    float s = 0.f;
    for (int n = 0; n < NS; n++) {
        int tok = samples[n * SB + j];
        const float* er = Egl + (size_t)tok * NHP;
        float part = 0.f;
        for (int c = tid; c < NHID; c += 128) {
            float v = tanh_fast(er[c] + hus[c]);
            float d = fl[c] - v;
            part += d * d;
        }
        #pragma unroll
        for (int o = 16; o > 0; o >>= 1) part += __shfl_down_sync(0xffffffffu, part, o);
        if ((tid & 31) == 0) red[tid >> 5] = part;
        __syncthreads();
        if (tid == 0) {
            float dist = red[0] + red[1] + red[2] + red[3] - bias[tok];
            s += __expf(-TEMP * dist);
        }
        __syncthreads();
    }
    if (tid == 0) NEGS[j] = s;
}

// ---------------- positives + log-sum reduction ----------------
__global__ __launch_bounds__(128) void k_pos(const int* __restrict__ data,
                                             const float* __restrict__ bias) {
    int j = blockIdx.x;
    __shared__ float red[4];
    const float* r0 = RO + (size_t)j * NHP;
    const float* r1 = RO + (size_t)(j + BATCH) * NHP;
    int tid = threadIdx.x;
    float part = 0.f;
    for (int c = tid; c < NHID; c += 128) {
        float d = r0[c] - r1[c];
        part += d * d;
    }
    #pragma unroll
    for (int o = 16; o > 0; o >>= 1) part += __shfl_down_sync(0xffffffffu, part, o);
    if ((tid & 31) == 0) red[tid >> 5] = part;
    __syncthreads();
    if (tid == 0) {
        float ss = red[0] + red[1] + red[2] + red[3];
        int tok = data[j];
        float pos = TEMP * (ss - bias[tok]);
        float se = __expf(-pos) + NEGS[j];
        atomicAdd(&ACCpos, (double)pos);
        atomicAdd(&ACClog, (double)logf(se + EPSV));
    }
}

__global__ void k_bias2(const float* __restrict__ bias) {
    __shared__ float sh[256];
    int i = blockIdx.x * blockDim.x + threadIdx.x;
    float v = 0.f;
    if (i < NTOKEN) { float b = bias[i]; v = b * b; }
    sh[threadIdx.x] = v;
    __syncthreads();
    for (int o = 128; o > 0; o >>= 1) {
        if (threadIdx.x < o) sh[threadIdx.x] += sh[threadIdx.x + o];
        __syncthreads();
    }
    if (threadIdx.x == 0) atomicAdd(&ACCbias, (double)sh[0]);
}

__global__ void k_final(float* out, int out_size) {
    if (out_size < 1) return;
    double loss = ACCpos / (double)SB + ACClog / (double)SB + ACCbias;
    out[0] = (float)loss;
}

__global__ void k_copyhid(float* out, int out_size) {
    int i = blockIdx.x * blockDim.x + threadIdx.x;
    if (i >= BATCH * NHID) return;
    if (1 + i < out_size) {
        int b = i / NHID, c = i % NHID;
        out[1 + i] = RO[(size_t)(SLEN * BATCH + b) * NHP + c];
    }
}

// ---------------- launch ----------------
extern "C" void kernel_launch(void* const* d_in, const int* in_sizes, int n_in,
                              void* d_out, int out_size) {
    const int*   data    = (const int*)d_in[0];
    const float* hidden  = (const float*)d_in[1];
    const int*   samples = (const int*)d_in[2];
    const float* emb_W   = (const float*)d_in[3];
    const float* W_ih    = (const float*)d_in[4];
    const float* b_ih    = (const float*)d_in[5];
    const float* W_hh    = (const float*)d_in[6];
    const float* b_hh    = (const float*)d_in[7];
    const float* bias    = (const float*)d_in[8];
    float* out = (float*)d_out;
    (void)in_sizes; (void)n_in;

    k_zero<<<4096, 256>>>();
    k_prep<<<4096, 256>>>(W_hh, W_ih, hidden);

    dim3 ge(9, 260);                 // 1152/128 x ceil(33278/128)
    k_egemm<<<ge, 256>>>(emb_W, b_ih);

    dim3 ga(18, 2, 4);               // N-tiles x M-tiles x K-splits
    const int nb = (BATCH * NHID + 255) / 256;
    for (int t = 0; t < SLEN; t++) {
        k_stepA<<<ga, 256>>>(t);
        k_stepB<<<nb, 256>>>(t, data, b_hh);
    }

    k_neg<<<SB, 128>>>(samples, bias);
    k_pos<<<SB, 128>>>(data, bias);
    k_bias2<<<(NTOKEN + 255) / 256, 256>>>(bias);
    k_final<<<1, 1>>>(out, out_size);
    k_copyhid<<<nb, 256>>>(out, out_size);
}

// round 2
// speedup vs baseline: 1.1825x; 1.1825x over previous
#include <cuda_runtime.h>

#define NTOKEN 33278
#define NINP   400
#define NHID   1150
#define NHP    1152          // padded row stride
#define SLEN   70
#define BATCH  128
#define NS     10
#define SB     (SLEN*BATCH)  // 8960
#define TEMP   65.0f
#define EPSV   1e-6f

// persistent scan config
#define NBLK   144           // 9 N-tiles x 16 K-splits  (<=148 SMs: co-resident)
#define KSPLIT 16
#define KCHUNK 72            // k per block
#define CSIZE  24            // inner staging chunk (3 per step)
#define NTILE  128

// ---------------- device scratch ----------------
__device__ __align__(16) float Egl[(size_t)NTOKEN * NHP];              // emb_W @ W_ih^T + b_ih
__device__ __align__(16) float RO[(size_t)(SLEN + 1) * BATCH * NHP];   // hidden states
__device__ __align__(16) float HU[(size_t)SLEN * BATCH * NHP];         // h@W_hh^T + b_hh
__device__ __align__(16) float WIH[NHP * NINP];                        // padded W_ih
__device__ __align__(16) float HUP[(size_t)KSPLIT * BATCH * NHP];      // split-K partials
__device__ double ACCpos, ACClog, ACCbias;
__device__ unsigned GBAR;

// ---------------- f32x2 helpers ----------------
typedef unsigned long long ull;
__device__ __forceinline__ ull pack2(float x, float y) {
    ull u; asm("mov.b64 %0, {%1, %2};" : "=l"(u) : "f"(x), "f"(y)); return u;
}
__device__ __forceinline__ float2 unpack2(ull u) {
    float2 r; asm("mov.b64 {%0, %1}, %2;" : "=f"(r.x), "=f"(r.y) : "l"(u)); return r;
}
__device__ __forceinline__ void fma2(ull &d, ull a, ull b) {
    asm("fma.rn.f32x2 %0, %1, %2, %3;" : "=l"(d) : "l"(a), "l"(b), "l"(d));
}
__device__ __forceinline__ float tanh_fast(float x) {
    float r; asm("tanh.approx.f32 %0, %1;" : "=f"(r) : "f"(x)); return r;
}

// ---------------- grid barrier (all NBLK blocks co-resident) ----------------
__device__ __forceinline__ void grid_bar(unsigned target) {
    __syncthreads();
    if (threadIdx.x == 0) {
        __threadfence();
        atomicAdd(&GBAR, 1u);
        unsigned v;
        do {
            asm volatile("ld.acquire.gpu.global.u32 %0, [%1];" : "=r"(v) : "l"(&GBAR) : "memory");
        } while (v < target);
    }
    __syncthreads();
}

// ---------------- init: reset accs/barrier, pad WIH, seed RO row 0 ----------------
__global__ void k_init(const float* __restrict__ W_ih, const float* __restrict__ hidden) {
    int i = blockIdx.x * blockDim.x + threadIdx.x;
    int stride = gridDim.x * blockDim.x;
    if (i == 0) { ACCpos = 0.0; ACClog = 0.0; ACCbias = 0.0; GBAR = 0u; }
    const int nwih = NHP * NINP;
    const int nrow0 = BATCH * NHP;
    for (int idx = i; idx < nwih + nrow0; idx += stride) {
        if (idx < nwih) {
            int r = idx / NINP;
            WIH[idx] = (r < NHID) ? W_ih[idx] : 0.f;
        } else {
            int j = idx - nwih;
            int b = j / NHP, c = j % NHP;
            RO[(size_t)b * NHP + c] = (c < NHID) ? hidden[b * NHID + c] : 0.f;
        }
    }
}

// ---------------- E = emb_W @ W_ih^T + b_ih  (double-buffered) ----------------
__global__ __launch_bounds__(256, 2) void k_egemm(const float* __restrict__ A,
                                                  const float* __restrict__ bih) {
    __shared__ float As[2][16][132];
    __shared__ float Bs[2][16][132];
    const int bm = blockIdx.y * 128;
    const int bn = blockIdx.x * 128;
    const int tid = threadIdx.x;
    const int tx = tid & 15, ty = tid >> 4;

    // staging coords (2 float4 each for A and B)
    int r0 = tid >> 2,            c40 = (tid & 3) * 4;
    int r1 = (tid + 256) >> 2,    c41 = ((tid + 256) & 3) * 4;

    ull acc[8][4];
    #pragma unroll
    for (int i = 0; i < 8; i++)
        #pragma unroll
        for (int j = 0; j < 4; j++) acc[i][j] = 0ULL;

    float4 va0, va1, vb0, vb1;
    auto LOAD = [&](int k0) {
        int m0 = bm + r0, m1 = bm + r1;
        va0 = (m0 < NTOKEN) ? *(const float4*)(A + (size_t)m0 * NINP + k0 + c40)
                            : make_float4(0.f, 0.f, 0.f, 0.f);
        va1 = (m1 < NTOKEN) ? *(const float4*)(A + (size_t)m1 * NINP + k0 + c41)
                            : make_float4(0.f, 0.f, 0.f, 0.f);
        vb0 = *(const float4*)(WIH + (size_t)(bn + r0) * NINP + k0 + c40);
        vb1 = *(const float4*)(WIH + (size_t)(bn + r1) * NINP + k0 + c41);
    };
    auto STORE = [&](int buf) {
        As[buf][c40 + 0][r0] = va0.x; As[buf][c40 + 1][r0] = va0.y;
        As[buf][c40 + 2][r0] = va0.z; As[buf][c40 + 3][r0] = va0.w;
        As[buf][c41 + 0][r1] = va1.x; As[buf][c41 + 1][r1] = va1.y;
        As[buf][c41 + 2][r1] = va1.z; As[buf][c41 + 3][r1] = va1.w;
        Bs[buf][c40 + 0][r0] = vb0.x; Bs[buf][c40 + 1][r0] = vb0.y;
        Bs[buf][c40 + 2][r0] = vb0.z; Bs[buf][c40 + 3][r0] = vb0.w;
        Bs[buf][c41 + 0][r1] = vb1.x; Bs[buf][c41 + 1][r1] = vb1.y;
        Bs[buf][c41 + 2][r1] = vb1.z; Bs[buf][c41 + 3][r1] = vb1.w;
    };

    LOAD(0); STORE(0);
    __syncthreads();

    const int NCH = NINP / 16;  // 25
    for (int c = 0; c < NCH; c++) {
        int buf = c & 1;
        if (c + 1 < NCH) LOAD((c + 1) * 16);
        #pragma unroll
        for (int kk = 0; kk < 16; kk++) {
            float4 a0 = *(const float4*)&As[buf][kk][ty * 8];
            float4 a1 = *(const float4*)&As[buf][kk][ty * 8 + 4];
            float4 b0 = *(const float4*)&Bs[buf][kk][tx * 8];
            float4 b1 = *(const float4*)&Bs[buf][kk][tx * 8 + 4];
            ull bb[4] = { pack2(b0.x, b0.y), pack2(b0.z, b0.w),
                          pack2(b1.x, b1.y), pack2(b1.z, b1.w) };
            float am[8] = {a0.x, a0.y, a0.z, a0.w, a1.x, a1.y, a1.z, a1.w};
            #pragma unroll
            for (int i = 0; i < 8; i++) {
                ull ad = pack2(am[i], am[i]);
                #pragma unroll
                for (int j = 0; j < 4; j++) fma2(acc[i][j], ad, bb[j]);
            }
        }
        if (c + 1 < NCH) {
            STORE(buf ^ 1);
            __syncthreads();
        }
    }

    #pragma unroll
    for (int i = 0; i < 8; i++) {
        int m = bm + ty * 8 + i;
        if (m >= NTOKEN) continue;
        float* crow = Egl + (size_t)m * NHP;
        #pragma unroll
        for (int j = 0; j < 4; j++) {
            float2 v = unpack2(acc[i][j]);
            int n = bn + tx * 8 + j * 2;
            if (n     < NHID) crow[n]     = v.x + bih[n];
            if (n + 1 < NHID) crow[n + 1] = v.y + bih[n + 1];
        }
    }
}

// ---------------- persistent scan: all 70 steps in one kernel ----------------
// block = (bn, kz): N-tile 128, K-chunk 72. Ws resident in smem for all steps.
#define SMEM_SCAN ((KCHUNK * 132 + 2 * CSIZE * 132) * 4)

__global__ __launch_bounds__(256) void k_scan(const int* __restrict__ data,
                                              const float* __restrict__ W_hh,
                                              const float* __restrict__ b_hh) {
    extern __shared__ float sm[];
    float* Ws = sm;                       // [KCHUNK][132]
    float* As = sm + KCHUNK * 132;        // [2][CSIZE][132]

    const int tid = threadIdx.x;
    const int bn = blockIdx.x / KSPLIT;
    const int kz = blockIdx.x % KSPLIT;
    const int kbase = kz * KCHUNK;
    const int tx = tid & 15, ty = tid >> 4;

    // load this block's W_hh slice once: Ws[k][n] = W_hh[bn*128+n][kbase+k]
    for (int idx = tid; idx < KCHUNK * NTILE; idx += 256) {
        int k = idx % KCHUNK, n = idx / KCHUNK;
        int gn = bn * NTILE + n, gk = kbase + k;
        Ws[k * 132 + n] = (gn < NHID && gk < NHID) ? W_hh[(size_t)gn * NHID + gk] : 0.f;
    }
    __syncthreads();

    // per-thread staging coords: 3 float4 covering 24k x 128m tile
    int mm[3], cc4[3];
    #pragma unroll
    for (int l = 0; l < 3; l++) {
        int f = tid + l * 256;
        mm[l] = f / 6;
        cc4[l] = (f % 6) * 4;
    }

    float* P = HUP + (size_t)kz * BATCH * NHP;
    unsigned barid = 0;

    for (int t = 0; t < SLEN; t++) {
        const float* Arow = RO + (size_t)t * BATCH * NHP;

        ull acc[8][4];
        #pragma unroll
        for (int i = 0; i < 8; i++)
            #pragma unroll
            for (int j = 0; j < 4; j++) acc[i][j] = 0ULL;

        float4 ra[3];
        #pragma unroll
        for (int l = 0; l < 3; l++)
            ra[l] = *(const float4*)(Arow + (size_t)mm[l] * NHP + kbase + cc4[l]);
        #pragma unroll
        for (int l = 0; l < 3; l++) {
            float* dst = As + (0) + cc4[l] * 132 + mm[l];
            dst[0] = ra[l].x; dst[132] = ra[l].y; dst[264] = ra[l].z; dst[396] = ra[l].w;
        }
        __syncthreads();

        for (int c = 0; c < 3; c++) {
            int buf = c & 1;
            if (c < 2) {
                #pragma unroll
                for (int l = 0; l < 3; l++)
                    ra[l] = *(const float4*)(Arow + (size_t)mm[l] * NHP + kbase + (c + 1) * CSIZE + cc4[l]);
            }
            const float* Ab = As + buf * CSIZE * 132;
            const float* Wc = Ws + c * CSIZE * 132;
            #pragma unroll
            for (int kk = 0; kk < CSIZE; kk++) {
                float4 a0 = *(const float4*)(Ab + kk * 132 + ty * 8);
                float4 a1 = *(const float4*)(Ab + kk * 132 + ty * 8 + 4);
                float4 b0 = *(const float4*)(Wc + kk * 132 + tx * 8);
                float4 b1 = *(const float4*)(Wc + kk * 132 + tx * 8 + 4);
                ull bb[4] = { pack2(b0.x, b0.y), pack2(b0.z, b0.w),
                              pack2(b1.x, b1.y), pack2(b1.z, b1.w) };
                float am[8] = {a0.x, a0.y, a0.z, a0.w, a1.x, a1.y, a1.z, a1.w};
                #pragma unroll
                for (int i = 0; i < 8; i++) {
                    ull ad = pack2(am[i], am[i]);
                    #pragma unroll
                    for (int j = 0; j < 4; j++) fma2(acc[i][j], ad, bb[j]);
                }
            }
            if (c < 2) {
                float* Anx = As + (buf ^ 1) * CSIZE * 132;
                #pragma unroll
                for (int l = 0; l < 3; l++) {
                    float* dst = Anx + cc4[l] * 132 + mm[l];
                    dst[0] = ra[l].x; dst[132] = ra[l].y; dst[264] = ra[l].z; dst[396] = ra[l].w;
                }
                __syncthreads();
            }
        }

        // write split-K partial
        #pragma unroll
        for (int i = 0; i < 8; i++) {
            float* prow = P + (size_t)(ty * 8 + i) * NHP + bn * NTILE;
            #pragma unroll
            for (int j = 0; j < 4; j++) {
                float2 v = unpack2(acc[i][j]);
                prow[tx * 8 + j * 2]     = v.x;
                prow[tx * 8 + j * 2 + 1] = v.y;
            }
        }

        barid++; grid_bar(barid * NBLK);

        // fused stepB: this block's 1024-element slice of [128 x 1152]
        {
            const int base = blockIdx.x * 1024;
            #pragma unroll
            for (int e = 0; e < 4; e++) {
                int i = base + e * 256 + tid;
                int b = i / NHP, ccol = i % NHP;
                float hu = 0.f;
                #pragma unroll
                for (int z = 0; z < KSPLIT; z++)
                    hu += HUP[(size_t)z * BATCH * NHP + i];
                size_t o1 = (size_t)(t + 1) * BATCH * NHP + i;
                size_t oh = (size_t)t * BATCH * NHP + i;
                if (ccol < NHID) {
                    hu += b_hh[ccol];
                    int tok = data[t * BATCH + b];
                    float pre = Egl[(size_t)tok * NHP + ccol] + hu;
                    RO[o1] = tanhf(pre);
                    HU[oh] = hu;
                } else {
                    RO[o1] = 0.f;
                    HU[oh] = 0.f;
                }
            }
        }

        barid++; grid_bar(barid * NBLK);
    }
}

// ---------------- fused negatives + positives per position j ----------------
__global__ __launch_bounds__(128) void k_negpos(const int* __restrict__ samples,
                                                const int* __restrict__ data,
                                                const float* __restrict__ bias) {
    int j = blockIdx.x;
    __shared__ float fl[NHID], hus[NHID];
    __shared__ float red[4];
    const float* flat = RO + (size_t)j * NHP;
    const float* nxt  = RO + (size_t)(j + BATCH) * NHP;
    const float* huj  = HU + (size_t)j * NHP;
    int tid = threadIdx.x;

    float pp = 0.f;
    for (int c = tid; c < NHID; c += 128) {
        float f = flat[c];
        float d = f - nxt[c];
        pp += d * d;
        fl[c] = f; hus[c] = huj[c];
    }
    #pragma unroll
    for (int o = 16; o > 0; o >>= 1) pp += __shfl_down_sync(0xffffffffu, pp, o);
    if ((tid & 31) == 0) red[tid >> 5] = pp;
    __syncthreads();
    float possum = red[0] + red[1] + red[2] + red[3];
    __syncthreads();

    float s = 0.f;
    for (int n = 0; n < NS; n++) {
        int tok = samples[n * SB + j];
        const float* er = Egl + (size_t)tok * NHP;
        float part = 0.f;
        for (int c = tid; c < NHID; c += 128) {
            float v = tanh_fast(er[c] + hus[c]);
            float d = fl[c] - v;
            part += d * d;
        }
        #pragma unroll
        for (int o = 16; o > 0; o >>= 1) part += __shfl_down_sync(0xffffffffu, part, o);
        if ((tid & 31) == 0) red[tid >> 5] = part;
        __syncthreads();
        if (tid == 0) {
            float dist = red[0] + red[1] + red[2] + red[3] - bias[tok];
            s += __expf(-TEMP * dist);
        }
        __syncthreads();
    }
    if (tid == 0) {
        float pos = TEMP * (possum - bias[data[j]]);
        float se = __expf(-pos) + s;
        atomicAdd(&ACCpos, (double)pos);
        atomicAdd(&ACClog, (double)logf(se + EPSV));
    }
}

__global__ void k_bias2(const float* __restrict__ bias) {
    __shared__ float sh[256];
    int i = blockIdx.x * blockDim.x + threadIdx.x;
    float v = 0.f;
    if (i < NTOKEN) { float b = bias[i]; v = b * b; }
    sh[threadIdx.x] = v;
    __syncthreads();
    for (int o = 128; o > 0; o >>= 1) {
        if (threadIdx.x < o) sh[threadIdx.x] += sh[threadIdx.x + o];
        __syncthreads();
    }
    if (threadIdx.x == 0) atomicAdd(&ACCbias, (double)sh[0]);
}

__global__ void k_final(float* out, int out_size) {
    if (out_size < 1) return;
    double loss = ACCpos / (double)SB + ACClog / (double)SB + ACCbias;
    out[0] = (float)loss;
}

__global__ void k_copyhid(float* out, int out_size) {
    int i = blockIdx.x * blockDim.x + threadIdx.x;
    if (i >= BATCH * NHID) return;
    if (1 + i < out_size) {
        int b = i / NHID, c = i % NHID;
        out[1 + i] = RO[(size_t)(SLEN * BATCH + b) * NHP + c];
    }
}

// ---------------- launch ----------------
extern "C" void kernel_launch(void* const* d_in, const int* in_sizes, int n_in,
                              void* d_out, int out_size) {
    const int*   data    = (const int*)d_in[0];
    const float* hidden  = (const float*)d_in[1];
    const int*   samples = (const int*)d_in[2];
    const float* emb_W   = (const float*)d_in[3];
    const float* W_ih    = (const float*)d_in[4];
    const float* b_ih    = (const float*)d_in[5];
    const float* W_hh    = (const float*)d_in[6];
    const float* b_hh    = (const float*)d_in[7];
    const float* bias    = (const float*)d_in[8];
    float* out = (float*)d_out;
    (void)in_sizes; (void)n_in;

    cudaFuncSetAttribute(k_scan, cudaFuncAttributeMaxDynamicSharedMemorySize, SMEM_SCAN);

    k_init<<<1024, 256>>>(W_ih, hidden);

    dim3 ge(9, 260);
    k_egemm<<<ge, 256>>>(emb_W, b_ih);

    k_scan<<<NBLK, 256, SMEM_SCAN>>>(data, W_hh, b_hh);

    k_negpos<<<SB, 128>>>(samples, data, bias);
    k_bias2<<<(NTOKEN + 255) / 256, 256>>>(bias);
    k_final<<<1, 1>>>(out, out_size);
    const int nb = (BATCH * NHID + 255) / 256;
    k_copyhid<<<nb, 256>>>(out, out_size);
}

// round 3
// speedup vs baseline: 1.3607x; 1.1508x over previous
#include <cuda_runtime.h>
#include <cuda_bf16.h>

#define NTOKEN 33278
#define NINP   400
#define NHID   1150
#define NHP    1152
#define SLEN   70
#define BATCH  128
#define NS     10
#define SB     (SLEN*BATCH)
#define TEMP   65.0f
#define EPSV   1e-6f

#define NBLK   144
#define KSPLIT 16
#define KCHUNK 72
#define NTILE  128

// ---------------- device scratch ----------------
__device__ __align__(16) float Egl[(size_t)NTOKEN * NHP];
__device__ __align__(16) __nv_bfloat16 EglH[(size_t)NTOKEN * NHP];
__device__ __align__(16) float RO[(size_t)(SLEN + 1) * BATCH * NHP];
__device__ __align__(16) float HU[(size_t)SLEN * BATCH * NHP];
__device__ __align__(16) float WIH[NHP * NINP];
__device__ __align__(16) float HUP[(size_t)KSPLIT * BATCH * NHP];
__device__ double ACCpos, ACClog, ACCbias;
__device__ unsigned GBAR;

// ---------------- f32x2 helpers ----------------
typedef unsigned long long ull;
__device__ __forceinline__ ull pack2(float x, float y) {
    ull u; asm("mov.b64 %0, {%1, %2};" : "=l"(u) : "f"(x), "f"(y)); return u;
}
__device__ __forceinline__ float2 unpack2(ull u) {
    float2 r; asm("mov.b64 {%0, %1}, %2;" : "=f"(r.x), "=f"(r.y) : "l"(u)); return r;
}
__device__ __forceinline__ void fma2(ull &d, ull a, ull b) {
    asm("fma.rn.f32x2 %0, %1, %2, %3;" : "=l"(d) : "l"(a), "l"(b), "l"(d));
}
__device__ __forceinline__ float tanh_fast(float x) {
    float r; asm("tanh.approx.f32 %0, %1;" : "=f"(r) : "f"(x)); return r;
}
__device__ __forceinline__ float ldcg(const float* p) {
    float v; asm volatile("ld.global.cg.f32 %0, [%1];" : "=f"(v) : "l"(p)); return v;
}

// ---------------- grid barrier ----------------
__device__ __forceinline__ void grid_bar(unsigned target) {
    __syncthreads();
    if (threadIdx.x == 0) {
        __threadfence();
        atomicAdd(&GBAR, 1u);
        unsigned v;
        do {
            asm volatile("ld.acquire.gpu.global.u32 %0, [%1];" : "=r"(v) : "l"(&GBAR) : "memory");
        } while (v < target);
    }
    __syncthreads();
}

// ---------------- init ----------------
__global__ void k_init(const float* __restrict__ W_ih, const float* __restrict__ hidden) {
    int i = blockIdx.x * blockDim.x + threadIdx.x;
    int stride = gridDim.x * blockDim.x;
    if (i == 0) { ACCpos = 0.0; ACClog = 0.0; ACCbias = 0.0; GBAR = 0u; }
    const int nwih = NHP * NINP;
    const int nrow0 = BATCH * NHP;
    for (int idx = i; idx < nwih + nrow0; idx += stride) {
        if (idx < nwih) {
            int r = idx / NINP;
            WIH[idx] = (r < NHID) ? W_ih[idx] : 0.f;
        } else {
            int j = idx - nwih;
            int b = j / NHP, c = j % NHP;
            RO[(size_t)b * NHP + c] = (c < NHID) ? hidden[b * NHID + c] : 0.f;
        }
    }
}

// ---------------- E = emb_W @ W_ih^T + b_ih ----------------
// 256 thr, tile 128x128, micro 16m x 4n: A broadcast, B conflict-free.
__global__ __launch_bounds__(256, 2) void k_egemm(const float* __restrict__ A,
                                                  const float* __restrict__ bih) {
    __shared__ float As[2][16][132];
    __shared__ float Bs[2][16][132];
    const int bm = blockIdx.y * 128;
    const int bn = blockIdx.x * 128;
    const int tid = threadIdx.x;
    const int tx = tid & 31, ty = tid >> 5;   // 32 n-groups x 8 m-groups

    int r0 = tid >> 2,         c40 = (tid & 3) * 4;
    int r1 = (tid + 256) >> 2, c41 = ((tid + 256) & 3) * 4;

    ull acc[16][2];
    #pragma unroll
    for (int i = 0; i < 16; i++) { acc[i][0] = 0ULL; acc[i][1] = 0ULL; }

    float4 va0, va1, vb0, vb1;
    auto LOAD = [&](int k0) {
        int m0 = bm + r0, m1 = bm + r1;
        va0 = (m0 < NTOKEN) ? *(const float4*)(A + (size_t)m0 * NINP + k0 + c40)
                            : make_float4(0.f, 0.f, 0.f, 0.f);
        va1 = (m1 < NTOKEN) ? *(const float4*)(A + (size_t)m1 * NINP + k0 + c41)
                            : make_float4(0.f, 0.f, 0.f, 0.f);
        vb0 = *(const float4*)(WIH + (size_t)(bn + r0) * NINP + k0 + c40);
        vb1 = *(const float4*)(WIH + (size_t)(bn + r1) * NINP + k0 + c41);
    };
    auto STORE = [&](int buf) {
        As[buf][c40 + 0][r0] = va0.x; As[buf][c40 + 1][r0] = va0.y;
        As[buf][c40 + 2][r0] = va0.z; As[buf][c40 + 3][r0] = va0.w;
        As[buf][c41 + 0][r1] = va1.x; As[buf][c41 + 1][r1] = va1.y;
        As[buf][c41 + 2][r1] = va1.z; As[buf][c41 + 3][r1] = va1.w;
        Bs[buf][c40 + 0][r0] = vb0.x; Bs[buf][c40 + 1][r0] = vb0.y;
        Bs[buf][c40 + 2][r0] = vb0.z; Bs[buf][c40 + 3][r0] = vb0.w;
        Bs[buf][c41 + 0][r1] = vb1.x; Bs[buf][c41 + 1][r1] = vb1.y;
        Bs[buf][c41 + 2][r1] = vb1.z; Bs[buf][c41 + 3][r1] = vb1.w;
    };

    LOAD(0); STORE(0);
    __syncthreads();

    const int NCH = NINP / 16;  // 25
    for (int c = 0; c < NCH; c++) {
        int buf = c & 1;
        if (c + 1 < NCH) LOAD((c + 1) * 16);
        #pragma unroll
        for (int kk = 0; kk < 16; kk++) {
            float4 a0 = *(const float4*)&As[buf][kk][ty * 16];
            float4 a1 = *(const float4*)&As[buf][kk][ty * 16 + 4];
            float4 a2 = *(const float4*)&As[buf][kk][ty * 16 + 8];
            float4 a3 = *(const float4*)&As[buf][kk][ty * 16 + 12];
            float4 b  = *(const float4*)&Bs[buf][kk][tx * 4];
            ull bb0 = pack2(b.x, b.y), bb1 = pack2(b.z, b.w);
            float am[16] = {a0.x, a0.y, a0.z, a0.w, a1.x, a1.y, a1.z, a1.w,
                            a2.x, a2.y, a2.z, a2.w, a3.x, a3.y, a3.z, a3.w};
            #pragma unroll
            for (int i = 0; i < 16; i++) {
                ull ad = pack2(am[i], am[i]);
                fma2(acc[i][0], ad, bb0);
                fma2(acc[i][1], ad, bb1);
            }
        }
        if (c + 1 < NCH) {
            STORE(buf ^ 1);
            __syncthreads();
        }
    }

    #pragma unroll
    for (int i = 0; i < 16; i++) {
        int m = bm + ty * 16 + i;
        if (m >= NTOKEN) continue;
        float* crow = Egl + (size_t)m * NHP;
        __nv_bfloat16* hrow = EglH + (size_t)m * NHP;
        int n0 = bn + tx * 4;
        float2 v0 = unpack2(acc[i][0]);
        float2 v1 = unpack2(acc[i][1]);
        float vals[4] = {v0.x, v0.y, v1.x, v1.y};
        if (n0 + 3 < NHID) {
            float4 o = make_float4(vals[0] + bih[n0], vals[1] + bih[n0 + 1],
                                   vals[2] + bih[n0 + 2], vals[3] + bih[n0 + 3]);
            *(float4*)(crow + n0) = o;
            hrow[n0]     = __float2bfloat16(o.x);
            hrow[n0 + 1] = __float2bfloat16(o.y);
            hrow[n0 + 2] = __float2bfloat16(o.z);
            hrow[n0 + 3] = __float2bfloat16(o.w);
        } else {
            #pragma unroll
            for (int j = 0; j < 4; j++) {
                int n = n0 + j;
                if (n < NHID) {
                    float o = vals[j] + bih[n];
                    crow[n] = o;
                    hrow[n] = __float2bfloat16(o);
                }
            }
        }
    }
}

// ---------------- persistent scan ----------------
// 144 blocks x 512 thr. block=(bn,kz): tile 128m x 128n, K-chunk 72.
#define SMEM_SCAN (2 * KCHUNK * 132 * 4)

__global__ __launch_bounds__(512) void k_scan(const int* __restrict__ data,
                                              const float* __restrict__ W_hh,
                                              const float* __restrict__ b_hh) {
    extern __shared__ float sm[];
    float* Ws = sm;                    // [72][132]
    float* As = sm + KCHUNK * 132;     // [72][132]

    const int tid = threadIdx.x;
    const int bn = blockIdx.x / KSPLIT;
    const int kz = blockIdx.x % KSPLIT;
    const int kbase = kz * KCHUNK;
    const int tx = tid & 31, ty = tid >> 5;   // 32 n-groups x 16 m-groups
    const int cb = tid >> 2;                   // batch row for As loads (0..127)
    const int cchunk = tid & 3;                // col chunk (x18)

    for (int idx = tid; idx < KCHUNK * NTILE; idx += 512) {
        int k = idx % KCHUNK, n = idx / KCHUNK;
        int gn = bn * NTILE + n, gk = kbase + k;
        Ws[k * 132 + n] = (gn < NHID && gk < NHID) ? W_hh[(size_t)gn * NHID + gk] : 0.f;
    }

    unsigned barid = 0;

    for (int t = 0; t < SLEN; t++) {
        // stage A = h_t[:, kbase..kbase+72) : coalesced reads, conflict-free writes
        const float* Ar = RO + (size_t)t * BATCH * NHP + (size_t)cb * NHP + kbase + cchunk * 18;
        #pragma unroll
        for (int s = 0; s < 18; s++) {
            As[(cchunk * 18 + s) * 132 + cb] = Ar[s];
        }
        __syncthreads();

        ull acc[8][2];
        #pragma unroll
        for (int i = 0; i < 8; i++) { acc[i][0] = 0ULL; acc[i][1] = 0ULL; }

        #pragma unroll 8
        for (int kk = 0; kk < KCHUNK; kk++) {
            float4 a0 = *(const float4*)&As[kk * 132 + ty * 8];
            float4 a1 = *(const float4*)&As[kk * 132 + ty * 8 + 4];
            float4 b  = *(const float4*)&Ws[kk * 132 + tx * 4];
            ull bb0 = pack2(b.x, b.y), bb1 = pack2(b.z, b.w);
            float am[8] = {a0.x, a0.y, a0.z, a0.w, a1.x, a1.y, a1.z, a1.w};
            #pragma unroll
            for (int i = 0; i < 8; i++) {
                ull ad = pack2(am[i], am[i]);
                fma2(acc[i][0], ad, bb0);
                fma2(acc[i][1], ad, bb1);
            }
        }

        // store split-K partials (coalesced float4)
        {
            float* P = HUP + (size_t)kz * BATCH * NHP + bn * NTILE;
            #pragma unroll
            for (int i = 0; i < 8; i++) {
                float2 v0 = unpack2(acc[i][0]);
                float2 v1 = unpack2(acc[i][1]);
                *(float4*)(P + (size_t)(ty * 8 + i) * NHP + tx * 4) =
                    make_float4(v0.x, v0.y, v1.x, v1.y);
            }
        }

        barid++; grid_bar(barid * NBLK);

        // combine: this block's 1024-elem slice of [128 x 1152]
        {
            const int base = blockIdx.x * 1024;
            #pragma unroll
            for (int e = 0; e < 2; e++) {
                int i = base + e * 512 + tid;
                int b = i / NHP, ccol = i % NHP;
                float hu = 0.f;
                #pragma unroll
                for (int z = 0; z < KSPLIT; z++)
                    hu += ldcg(HUP + (size_t)z * BATCH * NHP + i);
                size_t o1 = (size_t)(t + 1) * BATCH * NHP + i;
                size_t oh = (size_t)t * BATCH * NHP + i;
                if (ccol < NHID) {
                    hu += b_hh[ccol];
                    int tok = data[t * BATCH + b];
                    float pre = Egl[(size_t)tok * NHP + ccol] + hu;
                    RO[o1] = tanh_fast(pre);
                    HU[oh] = hu;
                } else {
                    RO[o1] = 0.f;
                    HU[oh] = 0.f;
                }
            }
        }

        barid++; grid_bar(barid * NBLK);
    }
}

// ---------------- fused negatives + positives (bf16 E gather) ----------------
__global__ __launch_bounds__(128) void k_negpos(const int* __restrict__ samples,
                                                const int* __restrict__ data,
                                                const float* __restrict__ bias) {
    int j = blockIdx.x;
    __shared__ float fl[NHID], hus[NHID];
    __shared__ float red[4];
    const float* flat = RO + (size_t)j * NHP;
    const float* nxt  = RO + (size_t)(j + BATCH) * NHP;
    const float* huj  = HU + (size_t)j * NHP;
    int tid = threadIdx.x;

    float pp = 0.f;
    for (int c = tid; c < NHID; c += 128) {
        float f = flat[c];
        float d = f - nxt[c];
        pp += d * d;
        fl[c] = f; hus[c] = huj[c];
    }
    #pragma unroll
    for (int o = 16; o > 0; o >>= 1) pp += __shfl_down_sync(0xffffffffu, pp, o);
    if ((tid & 31) == 0) red[tid >> 5] = pp;
    __syncthreads();
    float possum = red[0] + red[1] + red[2] + red[3];
    __syncthreads();

    float s = 0.f;
    for (int n = 0; n < NS; n++) {
        int tok = samples[n * SB + j];
        const __nv_bfloat16* er = EglH + (size_t)tok * NHP;
        float part = 0.f;
        for (int c = tid; c < NHID; c += 128) {
            float v = tanh_fast(__bfloat162float(er[c]) + hus[c]);
            float d = fl[c] - v;
            part += d * d;
        }
        #pragma unroll
        for (int o = 16; o > 0; o >>= 1) part += __shfl_down_sync(0xffffffffu, part, o);
        if ((tid & 31) == 0) red[tid >> 5] = part;
        __syncthreads();
        if (tid == 0) {
            float dist = red[0] + red[1] + red[2] + red[3] - bias[tok];
            s += __expf(-TEMP * dist);
        }
        __syncthreads();
    }
    if (tid == 0) {
        float pos = TEMP * (possum - bias[data[j]]);
        float se = __expf(-pos) + s;
        atomicAdd(&ACCpos, (double)pos);
        atomicAdd(&ACClog, (double)logf(se + EPSV));
    }
}

__global__ void k_bias2(const float* __restrict__ bias) {
    __shared__ float sh[256];
    int i = blockIdx.x * blockDim.x + threadIdx.x;
    float v = 0.f;
    if (i < NTOKEN) { float b = bias[i]; v = b * b; }
    sh[threadIdx.x] = v;
    __syncthreads();
    for (int o = 128; o > 0; o >>= 1) {
        if (threadIdx.x < o) sh[threadIdx.x] += sh[threadIdx.x + o];
        __syncthreads();
    }
    if (threadIdx.x == 0) atomicAdd(&ACCbias, (double)sh[0]);
}

__global__ void k_final(float* out, int out_size) {
    if (out_size < 1) return;
    double loss = ACCpos / (double)SB + ACClog / (double)SB + ACCbias;
    out[0] = (float)loss;
}

__global__ void k_copyhid(float* out, int out_size) {
    int i = blockIdx.x * blockDim.x + threadIdx.x;
    if (i >= BATCH * NHID) return;
    if (1 + i < out_size) {
        int b = i / NHID, c = i % NHID;
        out[1 + i] = RO[(size_t)(SLEN * BATCH + b) * NHP + c];
    }
}

// ---------------- launch ----------------
extern "C" void kernel_launch(void* const* d_in, const int* in_sizes, int n_in,
                              void* d_out, int out_size) {
    const int*   data    = (const int*)d_in[0];
    const float* hidden  = (const float*)d_in[1];
    const int*   samples = (const int*)d_in[2];
    const float* emb_W   = (const float*)d_in[3];
    const float* W_ih    = (const float*)d_in[4];
    const float* b_ih    = (const float*)d_in[5];
    const float* W_hh    = (const float*)d_in[6];
    const float* b_hh    = (const float*)d_in[7];
    const float* bias    = (const float*)d_in[8];
    float* out = (float*)d_out;
    (void)in_sizes; (void)n_in;

    cudaFuncSetAttribute(k_scan, cudaFuncAttributeMaxDynamicSharedMemorySize, SMEM_SCAN);

    k_init<<<1024, 256>>>(W_ih, hidden);

    dim3 ge(9, 260);
    k_egemm<<<ge, 256>>>(emb_W, b_ih);

    k_scan<<<NBLK, 512, SMEM_SCAN>>>(data, W_hh, b_hh);

    k_negpos<<<SB, 128>>>(samples, data, bias);
    k_bias2<<<(NTOKEN + 255) / 256, 256>>>(bias);
    k_final<<<1, 1>>>(out, out_size);
    const int nb = (BATCH * NHID + 255) / 256;
    k_copyhid<<<nb, 256>>>(out, out_size);
}

// round 6
// speedup vs baseline: 1.5634x; 1.1489x over previous
#include <cuda_runtime.h>
#include <cuda_bf16.h>
#include <cstdint>

#define NTOKEN 33278
#define NINP   400
#define KPAD   448
#define NHID   1150
#define NHP    1152
#define SLEN   70
#define BATCH  128
#define NS     10
#define SB     (SLEN*BATCH)
#define TEMP   65.0f
#define EPSV   1e-6f

#define NBLK   144
#define KSPLIT 16
#define KCHUNK 72
#define NTILE  128

// ---------------- device scratch ----------------
__device__ __align__(16) __nv_bfloat16 A448[(size_t)NTOKEN * KPAD];   // bf16 emb_W, K-padded
__device__ __align__(16) __nv_bfloat16 Wb448[(size_t)NHP * KPAD];     // bf16 W_ih, padded
__device__ __align__(16) __nv_bfloat16 EglH[(size_t)NTOKEN * NHP];    // bf16 E (negpos only)
__device__ __align__(16) float WIH[NHP * NINP];                       // fp32 W_ih padded
__device__ __align__(16) float scanE[(size_t)SB * NHP];               // fp32 E for gathered tokens
__device__ __align__(16) float RO[(size_t)(SLEN + 1) * BATCH * NHP];
__device__ __align__(16) float HU[(size_t)SLEN * BATCH * NHP];
__device__ __align__(16) float HUP[(size_t)KSPLIT * BATCH * NHP];
__device__ double ACCpos, ACClog, ACCbias;
__device__ unsigned GBAR;

// ---------------- f32x2 / misc helpers ----------------
typedef unsigned long long ull;
__device__ __forceinline__ ull pack2(float x, float y) {
    ull u; asm("mov.b64 %0, {%1, %2};" : "=l"(u) : "f"(x), "f"(y)); return u;
}
__device__ __forceinline__ float2 unpack2(ull u) {
    float2 r; asm("mov.b64 {%0, %1}, %2;" : "=f"(r.x), "=f"(r.y) : "l"(u)); return r;
}
__device__ __forceinline__ void fma2(ull &d, ull a, ull b) {
    asm("fma.rn.f32x2 %0, %1, %2, %3;" : "=l"(d) : "l"(a), "l"(b), "l"(d));
}
__device__ __forceinline__ float tanh_fast(float x) {
    float r; asm("tanh.approx.f32 %0, %1;" : "=f"(r) : "f"(x)); return r;
}
__device__ __forceinline__ float ldcg(const float* p) {
    float v; asm volatile("ld.global.cg.f32 %0, [%1];" : "=f"(v) : "l"(p)); return v;
}
__device__ __forceinline__ uint32_t smem_u32(const void* p) {
    uint32_t a;
    asm("{ .reg .u64 t; cvta.to.shared.u64 t, %1; cvt.u32.u64 %0, t; }" : "=r"(a) : "l"(p));
    return a;
}
#define SW128(o)   ((o) ^ (((o) >> 3) & 0x70))

// ---------------- HMMA helpers (base-ISA) ----------------
__device__ __forceinline__ void ldsm4(uint32_t* r, uint32_t addr) {
    asm volatile("ldmatrix.sync.aligned.m8n8.x4.shared.b16 {%0,%1,%2,%3}, [%4];"
                 : "=r"(r[0]), "=r"(r[1]), "=r"(r[2]), "=r"(r[3]) : "r"(addr));
}
__device__ __forceinline__ void mma16816(float* d, const uint32_t* a, uint32_t b0, uint32_t b1) {
    asm volatile(
        "mma.sync.aligned.m16n8k16.row.col.f32.bf16.bf16.f32 "
        "{%0,%1,%2,%3}, {%4,%5,%6,%7}, {%8,%9}, {%0,%1,%2,%3};"
        : "+f"(d[0]), "+f"(d[1]), "+f"(d[2]), "+f"(d[3])
        : "r"(a[0]), "r"(a[1]), "r"(a[2]), "r"(a[3]), "r"(b0), "r"(b1));
}

// ---------------- grid barrier ----------------
__device__ __forceinline__ void grid_bar(unsigned target) {
    __syncthreads();
    if (threadIdx.x == 0) {
        __threadfence();
        atomicAdd(&GBAR, 1u);
        unsigned v;
        do {
            asm volatile("ld.acquire.gpu.global.u32 %0, [%1];" : "=r"(v) : "l"(&GBAR) : "memory");
        } while (v < target);
    }
    __syncthreads();
}

// ---------------- init ----------------
__global__ void k_init(const float* __restrict__ hidden, const float* __restrict__ W_ih) {
    int i = blockIdx.x * blockDim.x + threadIdx.x;
    int stride = gridDim.x * blockDim.x;
    if (i == 0) { ACCpos = 0.0; ACClog = 0.0; ACCbias = 0.0; GBAR = 0u; }
    const int nwih = NHP * NINP;
    const int nrow0 = BATCH * NHP;
    for (int idx = i; idx < nwih + nrow0; idx += stride) {
        if (idx < nwih) {
            int r = idx / NINP;
            WIH[idx] = (r < NHID) ? W_ih[idx] : 0.f;
        } else {
            int j = idx - nwih;
            int b = j / NHP, c = j % NHP;
            RO[(size_t)b * NHP + c] = (c < NHID) ? hidden[b * NHID + c] : 0.f;
        }
    }
}

// ---------------- bf16 conversion / padding ----------------
__global__ void k_conv(const float* __restrict__ emb_W, const float* __restrict__ W_ih) {
    size_t i = (size_t)blockIdx.x * blockDim.x + threadIdx.x;
    size_t stride = (size_t)gridDim.x * blockDim.x;
    const size_t na = (size_t)NTOKEN * KPAD;
    const size_t nb = (size_t)NHP * KPAD;
    for (size_t idx = i; idx < na + nb; idx += stride) {
        if (idx < na) {
            size_t k = idx % KPAD;
            size_t m = idx / KPAD;
            A448[idx] = (k < NINP) ? __float2bfloat16(emb_W[m * NINP + k])
                                   : __float2bfloat16(0.f);
        } else {
            size_t j = idx - na;
            size_t k = j % KPAD;
            size_t n = j / KPAD;
            Wb448[j] = (n < NHID && k < NINP) ? __float2bfloat16(W_ih[n * NINP + k])
                                              : __float2bfloat16(0.f);
        }
    }
}

// ---------------- vocab E GEMM via HMMA (bf16, feeds negpos only) ----------------
__global__ __launch_bounds__(256) void k_egemm_mma(const float* __restrict__ bih) {
    __shared__ __align__(16) uint8_t smA[128 * 128];
    __shared__ __align__(16) uint8_t smB[128 * 128];
    __shared__ float bihs[128];

    const int tid = threadIdx.x, wid = tid >> 5, lane = tid & 31;
    const int bm = blockIdx.y * 128, bn = blockIdx.x * 128;
    const int wm = wid & 1, wn = wid >> 1;

    if (tid < 128) { int n = bn + tid; bihs[tid] = (n < NHID) ? bih[n] : 0.f; }

    const uint32_t sA = smem_u32(smA);
    const uint32_t sB = smem_u32(smB);

    float acc[4][4][4];
    #pragma unroll
    for (int mi = 0; mi < 4; mi++)
        #pragma unroll
        for (int nj = 0; nj < 4; nj++)
            #pragma unroll
            for (int f = 0; f < 4; f++) acc[mi][nj][f] = 0.f;

    const int grp = lane >> 3, lr = lane & 7;

    for (int ch = 0; ch < 7; ch++) {
        __syncthreads();
        #pragma unroll
        for (int i = 0; i < 4; i++) {
            int u = tid + i * 256;
            int row = u >> 3, c8 = u & 7;
            int m = bm + row; if (m >= NTOKEN) m = NTOKEN - 1;
            uint32_t swo = SW128((uint32_t)(row * 128 + c8 * 16));
            *(uint4*)(smA + swo) = *(const uint4*)(A448 + (size_t)m * KPAD + ch * 64 + c8 * 8);
            *(uint4*)(smB + swo) = *(const uint4*)(Wb448 + (size_t)(bn + row) * KPAD + ch * 64 + c8 * 8);
        }
        __syncthreads();

        #pragma unroll
        for (int k16 = 0; k16 < 4; k16++) {
            const int k0 = k16 * 16;
            uint32_t bfr[2][4];
            #pragma unroll
            for (int j = 0; j < 2; j++) {
                int row = wn * 32 + j * 16 + (grp & 1) * 8 + lr;
                int col = k0 + (grp >> 1) * 8;
                ldsm4(bfr[j], sB + SW128((uint32_t)(row * 128 + col * 2)));
            }
            #pragma unroll
            for (int mi = 0; mi < 4; mi++) {
                uint32_t afr[4];
                int row = wm * 64 + mi * 16 + (grp & 1) * 8 + lr;
                int col = k0 + (grp >> 1) * 8;
                ldsm4(afr, sA + SW128((uint32_t)(row * 128 + col * 2)));
                #pragma unroll
                for (int nj = 0; nj < 4; nj++) {
                    const uint32_t* bf = bfr[nj >> 1];
                    mma16816(acc[mi][nj], afr, bf[nj & 1], bf[2 + (nj & 1)]);
                }
            }
        }
    }

    #pragma unroll
    for (int mi = 0; mi < 4; mi++) {
        int row0 = wm * 64 + mi * 16 + (lane >> 2);
        int m0g = bm + row0, m1g = m0g + 8;
        #pragma unroll
        for (int nj = 0; nj < 4; nj++) {
            int cloc = wn * 32 + nj * 8 + (lane & 3) * 2;
            float b0 = bihs[cloc], b1 = bihs[cloc + 1];
            int n = bn + cloc;
            if (m0g < NTOKEN) {
                __nv_bfloat162 p = __floats2bfloat162_rn(acc[mi][nj][0] + b0, acc[mi][nj][1] + b1);
                *(__nv_bfloat162*)(EglH + (size_t)m0g * NHP + n) = p;
            }
            if (m1g < NTOKEN) {
                __nv_bfloat162 p = __floats2bfloat162_rn(acc[mi][nj][2] + b0, acc[mi][nj][3] + b1);
                *(__nv_bfloat162*)(EglH + (size_t)m1g * NHP + n) = p;
            }
        }
    }
}

// ---------------- fp32 scanE GEMM (gathered rows, feeds the scan) ----------------
// scanE[j][n] = sum_k emb_W[data[j]][k] * W_ih[n][k] + b_ih[n],  j in [0,8960)
__global__ __launch_bounds__(256, 2) void k_scane(const float* __restrict__ A,
                                                  const int* __restrict__ data,
                                                  const float* __restrict__ bih) {
    __shared__ float As[2][16][132];
    __shared__ float Bs[2][16][132];
    const int bm = blockIdx.y * 128;
    const int bn = blockIdx.x * 128;
    const int tid = threadIdx.x;
    const int tx = tid & 31, ty = tid >> 5;

    int r0 = tid >> 2,         c40 = (tid & 3) * 4;
    int r1 = (tid + 256) >> 2, c41 = ((tid + 256) & 3) * 4;
    const int tok0 = data[bm + r0];
    const int tok1 = data[bm + r1];

    ull acc[16][2];
    #pragma unroll
    for (int i = 0; i < 16; i++) { acc[i][0] = 0ULL; acc[i][1] = 0ULL; }

    float4 va0, va1, vb0, vb1;
    auto LOAD = [&](int k0) {
        va0 = *(const float4*)(A + (size_t)tok0 * NINP + k0 + c40);
        va1 = *(const float4*)(A + (size_t)tok1 * NINP + k0 + c41);
        vb0 = *(const float4*)(WIH + (size_t)(bn + r0) * NINP + k0 + c40);
        vb1 = *(const float4*)(WIH + (size_t)(bn + r1) * NINP + k0 + c41);
    };
    auto STORE = [&](int buf) {
        As[buf][c40 + 0][r0] = va0.x; As[buf][c40 + 1][r0] = va0.y;
        As[buf][c40 + 2][r0] = va0.z; As[buf][c40 + 3][r0] = va0.w;
        As[buf][c41 + 0][r1] = va1.x; As[buf][c41 + 1][r1] = va1.y;
        As[buf][c41 + 2][r1] = va1.z; As[buf][c41 + 3][r1] = va1.w;
        Bs[buf][c40 + 0][r0] = vb0.x; Bs[buf][c40 + 1][r0] = vb0.y;
        Bs[buf][c40 + 2][r0] = vb0.z; Bs[buf][c40 + 3][r0] = vb0.w;
        Bs[buf][c41 + 0][r1] = vb1.x; Bs[buf][c41 + 1][r1] = vb1.y;
        Bs[buf][c41 + 2][r1] = vb1.z; Bs[buf][c41 + 3][r1] = vb1.w;
    };

    LOAD(0); STORE(0);
    __syncthreads();

    const int NCH = NINP / 16;  // 25
    for (int c = 0; c < NCH; c++) {
        int buf = c & 1;
        if (c + 1 < NCH) LOAD((c + 1) * 16);
        #pragma unroll
        for (int kk = 0; kk < 16; kk++) {
            float4 a0 = *(const float4*)&As[buf][kk][ty * 16];
            float4 a1 = *(const float4*)&As[buf][kk][ty * 16 + 4];
            float4 a2 = *(const float4*)&As[buf][kk][ty * 16 + 8];
            float4 a3 = *(const float4*)&As[buf][kk][ty * 16 + 12];
            float4 b  = *(const float4*)&Bs[buf][kk][tx * 4];
            ull bb0 = pack2(b.x, b.y), bb1 = pack2(b.z, b.w);
            float am[16] = {a0.x, a0.y, a0.z, a0.w, a1.x, a1.y, a1.z, a1.w,
                            a2.x, a2.y, a2.z, a2.w, a3.x, a3.y, a3.z, a3.w};
            #pragma unroll
            for (int i = 0; i < 16; i++) {
                ull ad = pack2(am[i], am[i]);
                fma2(acc[i][0], ad, bb0);
                fma2(acc[i][1], ad, bb1);
            }
        }
        if (c + 1 < NCH) {
            STORE(buf ^ 1);
            __syncthreads();
        }
    }

    #pragma unroll
    for (int i = 0; i < 16; i++) {
        int j = bm + ty * 16 + i;
        float* crow = scanE + (size_t)j * NHP;
        int n0 = bn + tx * 4;
        float2 v0 = unpack2(acc[i][0]);
        float2 v1 = unpack2(acc[i][1]);
        float vals[4] = {v0.x, v0.y, v1.x, v1.y};
        if (n0 + 3 < NHID) {
            *(float4*)(crow + n0) = make_float4(vals[0] + bih[n0], vals[1] + bih[n0 + 1],
                                                vals[2] + bih[n0 + 2], vals[3] + bih[n0 + 3]);
        } else {
            #pragma unroll
            for (int q = 0; q < 4; q++) {
                int n = n0 + q;
                if (n < NHID) crow[n] = vals[q] + bih[n];
                else if (n < NHP) crow[n] = 0.f;
            }
        }
    }
}

// ---------------- persistent scan ----------------
#define SMEM_SCAN (2 * KCHUNK * 132 * 4)

__global__ __launch_bounds__(512) void k_scan(const float* __restrict__ W_hh,
                                              const float* __restrict__ b_hh) {
    extern __shared__ float smf[];
    float* Ws = smf;
    float* As = smf + KCHUNK * 132;

    const int tid = threadIdx.x;
    const int bn = blockIdx.x / KSPLIT;
    const int kz = blockIdx.x % KSPLIT;
    const int kbase = kz * KCHUNK;
    const int tx = tid & 31, ty = tid >> 5;
    const int cb = tid >> 2;
    const int cchunk = tid & 3;

    for (int idx = tid; idx < KCHUNK * NTILE; idx += 512) {
        int k = idx % KCHUNK, n = idx / KCHUNK;
        int gn = bn * NTILE + n, gk = kbase + k;
        Ws[k * 132 + n] = (gn < NHID && gk < NHID) ? W_hh[(size_t)gn * NHID + gk] : 0.f;
    }

    unsigned barid = 0;

    for (int t = 0; t < SLEN; t++) {
        const float* Ar = RO + (size_t)t * BATCH * NHP + (size_t)cb * NHP + kbase + cchunk * 18;
        #pragma unroll
        for (int s = 0; s < 18; s++)
            As[(cchunk * 18 + s) * 132 + cb] = Ar[s];
        __syncthreads();

        ull acc[8][2];
        #pragma unroll
        for (int i = 0; i < 8; i++) { acc[i][0] = 0ULL; acc[i][1] = 0ULL; }

        #pragma unroll 8
        for (int kk = 0; kk < KCHUNK; kk++) {
            float4 a0 = *(const float4*)&As[kk * 132 + ty * 8];
            float4 a1 = *(const float4*)&As[kk * 132 + ty * 8 + 4];
            float4 b  = *(const float4*)&Ws[kk * 132 + tx * 4];
            ull bb0 = pack2(b.x, b.y), bb1 = pack2(b.z, b.w);
            float am[8] = {a0.x, a0.y, a0.z, a0.w, a1.x, a1.y, a1.z, a1.w};
            #pragma unroll
            for (int i = 0; i < 8; i++) {
                ull ad = pack2(am[i], am[i]);
                fma2(acc[i][0], ad, bb0);
                fma2(acc[i][1], ad, bb1);
            }
        }

        {
            float* P = HUP + (size_t)kz * BATCH * NHP + bn * NTILE;
            #pragma unroll
            for (int i = 0; i < 8; i++) {
                float2 v0 = unpack2(acc[i][0]);
                float2 v1 = unpack2(acc[i][1]);
                *(float4*)(P + (size_t)(ty * 8 + i) * NHP + tx * 4) =
                    make_float4(v0.x, v0.y, v1.x, v1.y);
            }
        }

        barid++; grid_bar(barid * NBLK);

        {
            const int base = blockIdx.x * 1024;
            const float* Et = scanE + (size_t)t * BATCH * NHP;
            #pragma unroll
            for (int e = 0; e < 2; e++) {
                int i = base + e * 512 + tid;
                int ccol = i % NHP;
                float hu = 0.f;
                #pragma unroll
                for (int z = 0; z < KSPLIT; z++)
                    hu += ldcg(HUP + (size_t)z * BATCH * NHP + i);
                size_t o1 = (size_t)(t + 1) * BATCH * NHP + i;
                size_t oh = (size_t)t * BATCH * NHP + i;
                if (ccol < NHID) {
                    hu += b_hh[ccol];
                    float pre = Et[i] + hu;
                    RO[o1] = tanh_fast(pre);
                    HU[oh] = hu;
                } else {
                    RO[o1] = 0.f;
                    HU[oh] = 0.f;
                }
            }
        }

        barid++; grid_bar(barid * NBLK);
    }
}

// ---------------- fused negatives + positives ----------------
__global__ __launch_bounds__(128) void k_negpos(const int* __restrict__ samples,
                                                const int* __restrict__ data,
                                                const float* __restrict__ bias) {
    int j = blockIdx.x;
    __shared__ float fl[NHID], hus[NHID];
    __shared__ float red[4];
    const float* flat = RO + (size_t)j * NHP;
    const float* nxt  = RO + (size_t)(j + BATCH) * NHP;
    const float* huj  = HU + (size_t)j * NHP;
    int tid = threadIdx.x;

    float pp = 0.f;
    for (int c = tid; c < NHID; c += 128) {
        float f = flat[c];
        float d = f - nxt[c];
        pp += d * d;
        fl[c] = f; hus[c] = huj[c];
    }
    #pragma unroll
    for (int o = 16; o > 0; o >>= 1) pp += __shfl_down_sync(0xffffffffu, pp, o);
    if ((tid & 31) == 0) red[tid >> 5] = pp;
    __syncthreads();
    float possum = red[0] + red[1] + red[2] + red[3];
    __syncthreads();

    float s = 0.f;
    for (int n = 0; n < NS; n++) {
        int tok = samples[n * SB + j];
        const __nv_bfloat16* er = EglH + (size_t)tok * NHP;
        float part = 0.f;
        for (int c = tid; c < NHID; c += 128) {
            float v = tanh_fast(__bfloat162float(er[c]) + hus[c]);
            float d = fl[c] - v;
            part += d * d;
        }
        #pragma unroll
        for (int o = 16; o > 0; o >>= 1) part += __shfl_down_sync(0xffffffffu, part, o);
        if ((tid & 31) == 0) red[tid >> 5] = part;
        __syncthreads();
        if (tid == 0) {
            float dist = red[0] + red[1] + red[2] + red[3] - bias[tok];
            s += __expf(-TEMP * dist);
        }
        __syncthreads();
    }
    if (tid == 0) {
        float pos = TEMP * (possum - bias[data[j]]);
        float se = __expf(-pos) + s;
        atomicAdd(&ACCpos, (double)pos);
        atomicAdd(&ACClog, (double)logf(se + EPSV));
    }
}

__global__ void k_bias2(const float* __restrict__ bias) {
    __shared__ float sh[256];
    int i = blockIdx.x * blockDim.x + threadIdx.x;
    float v = 0.f;
    if (i < NTOKEN) { float b = bias[i]; v = b * b; }
    sh[threadIdx.x] = v;
    __syncthreads();
    for (int o = 128; o > 0; o >>= 1) {
        if (threadIdx.x < o) sh[threadIdx.x] += sh[threadIdx.x + o];
        __syncthreads();
    }
    if (threadIdx.x == 0) atomicAdd(&ACCbias, (double)sh[0]);
}

__global__ void k_final(float* out, int out_size) {
    if (out_size < 1) return;
    double loss = ACCpos / (double)SB + ACClog / (double)SB + ACCbias;
    out[0] = (float)loss;
}

__global__ void k_copyhid(float* out, int out_size) {
    int i = blockIdx.x * blockDim.x + threadIdx.x;
    if (i >= BATCH * NHID) return;
    if (1 + i < out_size) {
        int b = i / NHID, c = i % NHID;
        out[1 + i] = RO[(size_t)(SLEN * BATCH + b) * NHP + c];
    }
}

// ---------------- launch ----------------
extern "C" void kernel_launch(void* const* d_in, const int* in_sizes, int n_in,
                              void* d_out, int out_size) {
    const int*   data    = (const int*)d_in[0];
    const float* hidden  = (const float*)d_in[1];
    const int*   samples = (const int*)d_in[2];
    const float* emb_W   = (const float*)d_in[3];
    const float* W_ih    = (const float*)d_in[4];
    const float* b_ih    = (const float*)d_in[5];
    const float* W_hh    = (const float*)d_in[6];
    const float* b_hh    = (const float*)d_in[7];
    const float* bias    = (const float*)d_in[8];
    float* out = (float*)d_out;
    (void)in_sizes; (void)n_in;

    cudaFuncSetAttribute(k_scan, cudaFuncAttributeMaxDynamicSharedMemorySize, SMEM_SCAN);

    k_init<<<1024, 256>>>(hidden, W_ih);
    k_conv<<<8192, 256>>>(emb_W, W_ih);

    dim3 ge(9, 260);
    k_egemm_mma<<<ge, 256>>>(b_ih);

    dim3 gs(9, 70);
    k_scane<<<gs, 256>>>(emb_W, data, b_ih);

    k_scan<<<NBLK, 512, SMEM_SCAN>>>(W_hh, b_hh);

    k_negpos<<<SB, 128>>>(samples, data, bias);
    k_bias2<<<(NTOKEN + 255) / 256, 256>>>(bias);
    k_final<<<1, 1>>>(out, out_size);
    const int nb = (BATCH * NHID + 255) / 256;
    k_copyhid<<<nb, 256>>>(out, out_size);
}

// round 7
// speedup vs baseline: 1.8698x; 1.1960x over previous
#include <cuda_runtime.h>
#include <cuda_bf16.h>
#include <cstdint>

#define NTOKEN 33278
#define NINP   400
#define KPAD   448
#define NHID   1150
#define NHP    1152
#define SLEN   70
#define BATCH  128
#define NS     10
#define SB     (SLEN*BATCH)
#define TEMP   65.0f
#define EPSV   1e-6f

// persistent scan config: 18 n-tiles(64) x 8 k-splits(144)
#define NBLK   144
#define SC_KS  8
#define SC_KC  144
#define SC_PAD 152        // bf16 row stride (304B, ldmatrix conflict-free)

// ---------------- device scratch ----------------
__device__ __align__(16) __nv_bfloat16 A448[(size_t)NTOKEN * KPAD];
__device__ __align__(16) __nv_bfloat16 Wb448[(size_t)NHP * KPAD];
__device__ __align__(16) __nv_bfloat16 EglH[(size_t)NTOKEN * NHP];
__device__ __align__(16) float WIH[NHP * NINP];
__device__ __align__(16) float scanE[(size_t)SB * NHP];
__device__ __align__(16) float RO[(size_t)(SLEN + 1) * BATCH * NHP];
__device__ __align__(16) float HU[(size_t)SLEN * BATCH * NHP];
__device__ __align__(16) float HUP[(size_t)SC_KS * BATCH * NHP];
__device__ double ACCpos, ACClog, ACCbias;
__device__ unsigned GBAR;

// ---------------- f32x2 / misc helpers ----------------
typedef unsigned long long ull;
__device__ __forceinline__ ull pack2(float x, float y) {
    ull u; asm("mov.b64 %0, {%1, %2};" : "=l"(u) : "f"(x), "f"(y)); return u;
}
__device__ __forceinline__ float2 unpack2(ull u) {
    float2 r; asm("mov.b64 {%0, %1}, %2;" : "=f"(r.x), "=f"(r.y) : "l"(u)); return r;
}
__device__ __forceinline__ void fma2(ull &d, ull a, ull b) {
    asm("fma.rn.f32x2 %0, %1, %2, %3;" : "=l"(d) : "l"(a), "l"(b), "l"(d));
}
__device__ __forceinline__ float tanh_fast(float x) {
    float r; asm("tanh.approx.f32 %0, %1;" : "=f"(r) : "f"(x)); return r;
}
__device__ __forceinline__ float ldcg(const float* p) {
    float v; asm volatile("ld.global.cg.f32 %0, [%1];" : "=f"(v) : "l"(p)); return v;
}
__device__ __forceinline__ uint32_t smem_u32(const void* p) {
    uint32_t a;
    asm("{ .reg .u64 t; cvta.to.shared.u64 t, %1; cvt.u32.u64 %0, t; }" : "=r"(a) : "l"(p));
    return a;
}
#define SW128(o)   ((o) ^ (((o) >> 3) & 0x70))

// ---------------- HMMA helpers (base-ISA) ----------------
__device__ __forceinline__ void ldsm4(uint32_t* r, uint32_t addr) {
    asm volatile("ldmatrix.sync.aligned.m8n8.x4.shared.b16 {%0,%1,%2,%3}, [%4];"
                 : "=r"(r[0]), "=r"(r[1]), "=r"(r[2]), "=r"(r[3]) : "r"(addr));
}
__device__ __forceinline__ void mma16816(float* d, const uint32_t* a, uint32_t b0, uint32_t b1) {
    asm volatile(
        "mma.sync.aligned.m16n8k16.row.col.f32.bf16.bf16.f32 "
        "{%0,%1,%2,%3}, {%4,%5,%6,%7}, {%8,%9}, {%0,%1,%2,%3};"
        : "+f"(d[0]), "+f"(d[1]), "+f"(d[2]), "+f"(d[3])
        : "r"(a[0]), "r"(a[1]), "r"(a[2]), "r"(a[3]), "r"(b0), "r"(b1));
}

// ---------------- grid barrier ----------------
__device__ __forceinline__ void grid_bar(unsigned target) {
    __syncthreads();
    if (threadIdx.x == 0) {
        __threadfence();
        atomicAdd(&GBAR, 1u);
        unsigned v;
        do {
            asm volatile("ld.acquire.gpu.global.u32 %0, [%1];" : "=r"(v) : "l"(&GBAR) : "memory");
        } while (v < target);
    }
    __syncthreads();
}

// ---------------- init ----------------
__global__ void k_init(const float* __restrict__ hidden, const float* __restrict__ W_ih) {
    int i = blockIdx.x * blockDim.x + threadIdx.x;
    int stride = gridDim.x * blockDim.x;
    if (i == 0) { ACCpos = 0.0; ACClog = 0.0; ACCbias = 0.0; GBAR = 0u; }
    const int nwih = NHP * NINP;
    const int nrow0 = BATCH * NHP;
    for (int idx = i; idx < nwih + nrow0; idx += stride) {
        if (idx < nwih) {
            int r = idx / NINP;
            WIH[idx] = (r < NHID) ? W_ih[idx] : 0.f;
        } else {
            int j = idx - nwih;
            int b = j / NHP, c = j % NHP;
            RO[(size_t)b * NHP + c] = (c < NHID) ? hidden[b * NHID + c] : 0.f;
        }
    }
}

// ---------------- bf16 conversion / padding ----------------
__global__ void k_conv(const float* __restrict__ emb_W, const float* __restrict__ W_ih) {
    size_t i = (size_t)blockIdx.x * blockDim.x + threadIdx.x;
    size_t stride = (size_t)gridDim.x * blockDim.x;
    const size_t na = (size_t)NTOKEN * KPAD;
    const size_t nb = (size_t)NHP * KPAD;
    for (size_t idx = i; idx < na + nb; idx += stride) {
        if (idx < na) {
            size_t k = idx % KPAD;
            size_t m = idx / KPAD;
            A448[idx] = (k < NINP) ? __float2bfloat16(emb_W[m * NINP + k])
                                   : __float2bfloat16(0.f);
        } else {
            size_t j = idx - na;
            size_t k = j % KPAD;
            size_t n = j / KPAD;
            Wb448[j] = (n < NHID && k < NINP) ? __float2bfloat16(W_ih[n * NINP + k])
                                              : __float2bfloat16(0.f);
        }
    }
}

// ---------------- vocab E GEMM via HMMA (bf16, negpos only) ----------------
__global__ __launch_bounds__(256) void k_egemm_mma(const float* __restrict__ bih) {
    __shared__ __align__(16) uint8_t smA[128 * 128];
    __shared__ __align__(16) uint8_t smB[128 * 128];
    __shared__ float bihs[128];

    const int tid = threadIdx.x, wid = tid >> 5, lane = tid & 31;
    const int bm = blockIdx.y * 128, bn = blockIdx.x * 128;
    const int wm = wid & 1, wn = wid >> 1;

    if (tid < 128) { int n = bn + tid; bihs[tid] = (n < NHID) ? bih[n] : 0.f; }

    const uint32_t sA = smem_u32(smA);
    const uint32_t sB = smem_u32(smB);

    float acc[4][4][4];
    #pragma unroll
    for (int mi = 0; mi < 4; mi++)
        #pragma unroll
        for (int nj = 0; nj < 4; nj++)
            #pragma unroll
            for (int f = 0; f < 4; f++) acc[mi][nj][f] = 0.f;

    const int grp = lane >> 3, lr = lane & 7;

    for (int ch = 0; ch < 7; ch++) {
        __syncthreads();
        #pragma unroll
        for (int i = 0; i < 4; i++) {
            int u = tid + i * 256;
            int row = u >> 3, c8 = u & 7;
            int m = bm + row; if (m >= NTOKEN) m = NTOKEN - 1;
            uint32_t swo = SW128((uint32_t)(row * 128 + c8 * 16));
            *(uint4*)(smA + swo) = *(const uint4*)(A448 + (size_t)m * KPAD + ch * 64 + c8 * 8);
            *(uint4*)(smB + swo) = *(const uint4*)(Wb448 + (size_t)(bn + row) * KPAD + ch * 64 + c8 * 8);
        }
        __syncthreads();

        #pragma unroll
        for (int k16 = 0; k16 < 4; k16++) {
            const int k0 = k16 * 16;
            uint32_t bfr[2][4];
            #pragma unroll
            for (int j = 0; j < 2; j++) {
                int row = wn * 32 + j * 16 + (grp & 1) * 8 + lr;
                int col = k0 + (grp >> 1) * 8;
                ldsm4(bfr[j], sB + SW128((uint32_t)(row * 128 + col * 2)));
            }
            #pragma unroll
            for (int mi = 0; mi < 4; mi++) {
                uint32_t afr[4];
                int row = wm * 64 + mi * 16 + (grp & 1) * 8 + lr;
                int col = k0 + (grp >> 1) * 8;
                ldsm4(afr, sA + SW128((uint32_t)(row * 128 + col * 2)));
                #pragma unroll
                for (int nj = 0; nj < 4; nj++) {
                    const uint32_t* bf = bfr[nj >> 1];
                    mma16816(acc[mi][nj], afr, bf[nj & 1], bf[2 + (nj & 1)]);
                }
            }
        }
    }

    #pragma unroll
    for (int mi = 0; mi < 4; mi++) {
        int row0 = wm * 64 + mi * 16 + (lane >> 2);
        int m0g = bm + row0, m1g = m0g + 8;
        #pragma unroll
        for (int nj = 0; nj < 4; nj++) {
            int cloc = wn * 32 + nj * 8 + (lane & 3) * 2;
            float b0 = bihs[cloc], b1 = bihs[cloc + 1];
            int n = bn + cloc;
            if (m0g < NTOKEN) {
                __nv_bfloat162 p = __floats2bfloat162_rn(acc[mi][nj][0] + b0, acc[mi][nj][1] + b1);
                *(__nv_bfloat162*)(EglH + (size_t)m0g * NHP + n) = p;
            }
            if (m1g < NTOKEN) {
                __nv_bfloat162 p = __floats2bfloat162_rn(acc[mi][nj][2] + b0, acc[mi][nj][3] + b1);
                *(__nv_bfloat162*)(EglH + (size_t)m1g * NHP + n) = p;
            }
        }
    }
}

// ---------------- fp32 scanE GEMM (gathered rows, feeds the scan) ----------------
__global__ __launch_bounds__(256, 2) void k_scane(const float* __restrict__ A,
                                                  const int* __restrict__ data,
                                                  const float* __restrict__ bih) {
    __shared__ float As[2][16][132];
    __shared__ float Bs[2][16][132];
    const int bm = blockIdx.y * 128;
    const int bn = blockIdx.x * 128;
    const int tid = threadIdx.x;
    const int tx = tid & 31, ty = tid >> 5;

    int r0 = tid >> 2,         c40 = (tid & 3) * 4;
    int r1 = (tid + 256) >> 2, c41 = ((tid + 256) & 3) * 4;
    const int tok0 = data[bm + r0];
    const int tok1 = data[bm + r1];

    ull acc[16][2];
    #pragma unroll
    for (int i = 0; i < 16; i++) { acc[i][0] = 0ULL; acc[i][1] = 0ULL; }

    float4 va0, va1, vb0, vb1;
    auto LOAD = [&](int k0) {
        va0 = *(const float4*)(A + (size_t)tok0 * NINP + k0 + c40);
        va1 = *(const float4*)(A + (size_t)tok1 * NINP + k0 + c41);
        vb0 = *(const float4*)(WIH + (size_t)(bn + r0) * NINP + k0 + c40);
        vb1 = *(const float4*)(WIH + (size_t)(bn + r1) * NINP + k0 + c41);
    };
    auto STORE = [&](int buf) {
        As[buf][c40 + 0][r0] = va0.x; As[buf][c40 + 1][r0] = va0.y;
        As[buf][c40 + 2][r0] = va0.z; As[buf][c40 + 3][r0] = va0.w;
        As[buf][c41 + 0][r1] = va1.x; As[buf][c41 + 1][r1] = va1.y;
        As[buf][c41 + 2][r1] = va1.z; As[buf][c41 + 3][r1] = va1.w;
        Bs[buf][c40 + 0][r0] = vb0.x; Bs[buf][c40 + 1][r0] = vb0.y;
        Bs[buf][c40 + 2][r0] = vb0.z; Bs[buf][c40 + 3][r0] = vb0.w;
        Bs[buf][c41 + 0][r1] = vb1.x; Bs[buf][c41 + 1][r1] = vb1.y;
        Bs[buf][c41 + 2][r1] = vb1.z; Bs[buf][c41 + 3][r1] = vb1.w;
    };

    LOAD(0); STORE(0);
    __syncthreads();

    const int NCH = NINP / 16;
    for (int c = 0; c < NCH; c++) {
        int buf = c & 1;
        if (c + 1 < NCH) LOAD((c + 1) * 16);
        #pragma unroll
        for (int kk = 0; kk < 16; kk++) {
            float4 a0 = *(const float4*)&As[buf][kk][ty * 16];
            float4 a1 = *(const float4*)&As[buf][kk][ty * 16 + 4];
            float4 a2 = *(const float4*)&As[buf][kk][ty * 16 + 8];
            float4 a3 = *(const float4*)&As[buf][kk][ty * 16 + 12];
            float4 b  = *(const float4*)&Bs[buf][kk][tx * 4];
            ull bb0 = pack2(b.x, b.y), bb1 = pack2(b.z, b.w);
            float am[16] = {a0.x, a0.y, a0.z, a0.w, a1.x, a1.y, a1.z, a1.w,
                            a2.x, a2.y, a2.z, a2.w, a3.x, a3.y, a3.z, a3.w};
            #pragma unroll
            for (int i = 0; i < 16; i++) {
                ull ad = pack2(am[i], am[i]);
                fma2(acc[i][0], ad, bb0);
                fma2(acc[i][1], ad, bb1);
            }
        }
        if (c + 1 < NCH) {
            STORE(buf ^ 1);
            __syncthreads();
        }
    }

    #pragma unroll
    for (int i = 0; i < 16; i++) {
        int j = bm + ty * 16 + i;
        float* crow = scanE + (size_t)j * NHP;
        int n0 = bn + tx * 4;
        float2 v0 = unpack2(acc[i][0]);
        float2 v1 = unpack2(acc[i][1]);
        float vals[4] = {v0.x, v0.y, v1.x, v1.y};
        if (n0 + 3 < NHID) {
            *(float4*)(crow + n0) = make_float4(vals[0] + bih[n0], vals[1] + bih[n0 + 1],
                                                vals[2] + bih[n0 + 2], vals[3] + bih[n0 + 3]);
        } else {
            #pragma unroll
            for (int q = 0; q < 4; q++) {
                int n = n0 + q;
                if (n < NHID) crow[n] = vals[q] + bih[n];
                else if (n < NHP) crow[n] = 0.f;
            }
        }
    }
}

// ---------------- persistent scan: bf16-split HMMA recurrent GEMM ----------------
// block=(bn,kz): tile 128m x 64n x 144k. 512 thr = 16 warps (4m x 4n).
#define SMEM_SCAN (2 * 128 * SC_PAD * 2 + 2 * 64 * SC_PAD * 2)

__global__ __launch_bounds__(512) void k_scan(const float* __restrict__ W_hh,
                                              const float* __restrict__ b_hh) {
    extern __shared__ char smc[];
    __nv_bfloat16* Ahi = (__nv_bfloat16*)smc;            // [128][SC_PAD]
    __nv_bfloat16* Alo = Ahi + 128 * SC_PAD;
    __nv_bfloat16* Whi = Alo + 128 * SC_PAD;             // [64][SC_PAD]
    __nv_bfloat16* Wlo = Whi + 64 * SC_PAD;
    const uint32_t sAhi = smem_u32(Ahi), sAlo = smem_u32(Alo);
    const uint32_t sWhi = smem_u32(Whi), sWlo = smem_u32(Wlo);

    const int tid = threadIdx.x, wid = tid >> 5, lane = tid & 31;
    const int bn = blockIdx.x / SC_KS;      // 0..17
    const int kz = blockIdx.x % SC_KS;      // 0..7
    const int kbase = kz * SC_KC;
    const int wm = wid & 3, wn = wid >> 2;  // 4m x 4n warps
    const int grp = lane >> 3, lr = lane & 7;

    // load + split W slice once: Whi/Wlo[n][k], n<64, k<144
    for (int idx = tid; idx < 64 * SC_KC; idx += 512) {
        int n = idx / SC_KC, k = idx % SC_KC;
        int gn = bn * 64 + n, gk = kbase + k;
        float w = (gn < NHID && gk < NHID) ? W_hh[(size_t)gn * NHID + gk] : 0.f;
        __nv_bfloat16 hi = __float2bfloat16(w);
        float lo = w - __bfloat162float(hi);
        Whi[n * SC_PAD + k] = hi;
        Wlo[n * SC_PAD + k] = __float2bfloat16(lo);
    }

    const int cb = tid >> 2;          // A-staging row (0..127)
    const int cc = (tid & 3) * 36;    // A-staging col base

    unsigned barid = 0;

    for (int t = 0; t < SLEN; t++) {
        // stage h_t slice, split hi/lo
        {
            const float* Ar = RO + (size_t)t * BATCH * NHP + (size_t)cb * NHP + kbase + cc;
            #pragma unroll
            for (int s = 0; s < 9; s++) {
                float4 v = *(const float4*)(Ar + s * 4);
                float vs[4] = {v.x, v.y, v.z, v.w};
                __nv_bfloat16 h[4]; __nv_bfloat16 l[4];
                #pragma unroll
                for (int e = 0; e < 4; e++) {
                    h[e] = __float2bfloat16(vs[e]);
                    l[e] = __float2bfloat16(vs[e] - __bfloat162float(h[e]));
                }
                int col = cc + s * 4;
                *(__nv_bfloat162*)(Ahi + cb * SC_PAD + col)     = *(__nv_bfloat162*)&h[0];
                *(__nv_bfloat162*)(Ahi + cb * SC_PAD + col + 2) = *(__nv_bfloat162*)&h[2];
                *(__nv_bfloat162*)(Alo + cb * SC_PAD + col)     = *(__nv_bfloat162*)&l[0];
                *(__nv_bfloat162*)(Alo + cb * SC_PAD + col + 2) = *(__nv_bfloat162*)&l[2];
            }
        }
        __syncthreads();

        float acc[2][2][4];
        #pragma unroll
        for (int mi = 0; mi < 2; mi++)
            #pragma unroll
            for (int nj = 0; nj < 2; nj++)
                #pragma unroll
                for (int f = 0; f < 4; f++) acc[mi][nj][f] = 0.f;

        #pragma unroll
        for (int k16 = 0; k16 < 9; k16++) {
            const int col = k16 * 16 + (grp >> 1) * 8;
            const int brow = wn * 16 + (grp & 1) * 8 + lr;
            uint32_t bh[4], bl[4];
            ldsm4(bh, sWhi + (uint32_t)(brow * (SC_PAD * 2) + col * 2));
            ldsm4(bl, sWlo + (uint32_t)(brow * (SC_PAD * 2) + col * 2));
            #pragma unroll
            for (int mi = 0; mi < 2; mi++) {
                const int arow = wm * 32 + mi * 16 + (grp & 1) * 8 + lr;
                uint32_t ah[4], al[4];
                ldsm4(ah, sAhi + (uint32_t)(arow * (SC_PAD * 2) + col * 2));
                ldsm4(al, sAlo + (uint32_t)(arow * (SC_PAD * 2) + col * 2));
                #pragma unroll
                for (int nj = 0; nj < 2; nj++) {
                    mma16816(acc[mi][nj], ah, bh[nj], bh[2 + nj]);  // hi*hi
                    mma16816(acc[mi][nj], ah, bl[nj], bl[2 + nj]);  // hi*lo
                    mma16816(acc[mi][nj], al, bh[nj], bh[2 + nj]);  // lo*hi
                }
            }
        }

        // store split-K partials
        {
            float* P = HUP + (size_t)kz * BATCH * NHP + bn * 64;
            #pragma unroll
            for (int mi = 0; mi < 2; mi++) {
                int r0 = wm * 32 + mi * 16 + (lane >> 2);
                #pragma unroll
                for (int nj = 0; nj < 2; nj++) {
                    int c0 = wn * 16 + nj * 8 + (lane & 3) * 2;
                    *(float2*)(P + (size_t)r0 * NHP + c0) =
                        make_float2(acc[mi][nj][0], acc[mi][nj][1]);
                    *(float2*)(P + (size_t)(r0 + 8) * NHP + c0) =
                        make_float2(acc[mi][nj][2], acc[mi][nj][3]);
                }
            }
        }

        barid++; grid_bar(barid * NBLK);

        // combine: this block's 1024-elem slice
        {
            const int base = blockIdx.x * 1024;
            const float* Et = scanE + (size_t)t * BATCH * NHP;
            #pragma unroll
            for (int e = 0; e < 2; e++) {
                int i = base + e * 512 + tid;
                int ccol = i % NHP;
                float hu = 0.f;
                #pragma unroll
                for (int z = 0; z < SC_KS; z++)
                    hu += ldcg(HUP + (size_t)z * BATCH * NHP + i);
                size_t o1 = (size_t)(t + 1) * BATCH * NHP + i;
                size_t oh = (size_t)t * BATCH * NHP + i;
                if (ccol < NHID) {
                    hu += b_hh[ccol];
                    float pre = Et[i] + hu;
                    RO[o1] = tanh_fast(pre);
                    HU[oh] = hu;
                } else {
                    RO[o1] = 0.f;
                    HU[oh] = 0.f;
                }
            }
        }

        barid++; grid_bar(barid * NBLK);
    }
}

// ---------------- fused negatives + positives ----------------
__global__ __launch_bounds__(128) void k_negpos(const int* __restrict__ samples,
                                                const int* __restrict__ data,
                                                const float* __restrict__ bias) {
    int j = blockIdx.x;
    __shared__ float fl[NHID], hus[NHID];
    __shared__ float red[4];
    const float* flat = RO + (size_t)j * NHP;
    const float* nxt  = RO + (size_t)(j + BATCH) * NHP;
    const float* huj  = HU + (size_t)j * NHP;
    int tid = threadIdx.x;

    float pp = 0.f;
    for (int c = tid; c < NHID; c += 128) {
        float f = flat[c];
        float d = f - nxt[c];
        pp += d * d;
        fl[c] = f; hus[c] = huj[c];
    }
    #pragma unroll
    for (int o = 16; o > 0; o >>= 1) pp += __shfl_down_sync(0xffffffffu, pp, o);
    if ((tid & 31) == 0) red[tid >> 5] = pp;
    __syncthreads();
    float possum = red[0] + red[1] + red[2] + red[3];
    __syncthreads();

    float s = 0.f;
    for (int n = 0; n < NS; n++) {
        int tok = samples[n * SB + j];
        const __nv_bfloat16* er = EglH + (size_t)tok * NHP;
        float part = 0.f;
        for (int c = tid; c < NHID; c += 128) {
            float v = tanh_fast(__bfloat162float(er[c]) + hus[c]);
            float d = fl[c] - v;
            part += d * d;
        }
        #pragma unroll
        for (int o = 16; o > 0; o >>= 1) part += __shfl_down_sync(0xffffffffu, part, o);
        if ((tid & 31) == 0) red[tid >> 5] = part;
        __syncthreads();
        if (tid == 0) {
            float dist = red[0] + red[1] + red[2] + red[3] - bias[tok];
            s += __expf(-TEMP * dist);
        }
        __syncthreads();
    }
    if (tid == 0) {
        float pos = TEMP * (possum - bias[data[j]]);
        float se = __expf(-pos) + s;
        atomicAdd(&ACCpos, (double)pos);
        atomicAdd(&ACClog, (double)logf(se + EPSV));
    }
}

__global__ void k_bias2(const float* __restrict__ bias) {
    __shared__ float sh[256];
    int i = blockIdx.x * blockDim.x + threadIdx.x;
    float v = 0.f;
    if (i < NTOKEN) { float b = bias[i]; v = b * b; }
    sh[threadIdx.x] = v;
    __syncthreads();
    for (int o = 128; o > 0; o >>= 1) {
        if (threadIdx.x < o) sh[threadIdx.x] += sh[threadIdx.x + o];
        __syncthreads();
    }
    if (threadIdx.x == 0) atomicAdd(&ACCbias, (double)sh[0]);
}

__global__ void k_final(float* out, int out_size) {
    if (out_size < 1) return;
    double loss = ACCpos / (double)SB + ACClog / (double)SB + ACCbias;
    out[0] = (float)loss;
}

__global__ void k_copyhid(float* out, int out_size) {
    int i = blockIdx.x * blockDim.x + threadIdx.x;
    if (i >= BATCH * NHID) return;
    if (1 + i < out_size) {
        int b = i / NHID, c = i % NHID;
        out[1 + i] = RO[(size_t)(SLEN * BATCH + b) * NHP + c];
    }
}

// ---------------- launch ----------------
extern "C" void kernel_launch(void* const* d_in, const int* in_sizes, int n_in,
                              void* d_out, int out_size) {
    const int*   data    = (const int*)d_in[0];
    const float* hidden  = (const float*)d_in[1];
    const int*   samples = (const int*)d_in[2];
    const float* emb_W   = (const float*)d_in[3];
    const float* W_ih    = (const float*)d_in[4];
    const float* b_ih    = (const float*)d_in[5];
    const float* W_hh    = (const float*)d_in[6];
    const float* b_hh    = (const float*)d_in[7];
    const float* bias    = (const float*)d_in[8];
    float* out = (float*)d_out;
    (void)in_sizes; (void)n_in;

    cudaFuncSetAttribute(k_scan, cudaFuncAttributeMaxDynamicSharedMemorySize, SMEM_SCAN);

    k_init<<<1024, 256>>>(hidden, W_ih);
    k_conv<<<8192, 256>>>(emb_W, W_ih);

    dim3 ge(9, 260);
    k_egemm_mma<<<ge, 256>>>(b_ih);

    dim3 gs(9, 70);
    k_scane<<<gs, 256>>>(emb_W, data, b_ih);

    k_scan<<<NBLK, 512, SMEM_SCAN>>>(W_hh, b_hh);

    k_negpos<<<SB, 128>>>(samples, data, bias);
    k_bias2<<<(NTOKEN + 255) / 256, 256>>>(bias);
    k_final<<<1, 1>>>(out, out_size);
    const int nb = (BATCH * NHID + 255) / 256;
    k_copyhid<<<nb, 256>>>(out, out_size);
}